// round 6
// baseline (speedup 1.0000x reference)
#include <cuda_runtime.h>
#include <cuda_fp16.h>
#include <cstdint>
#include <cstddef>

#define EPS 1e-8f
#define B_   16
#define CIN  128
#define COUT 128
#define HH   128
#define WW   128
#define SS   512
#define NTAP 9

// ---------------- scratch (__device__ globals; no allocs allowed) ----------
__device__ float  g_s[B_ * CIN];
__device__ __half g_wA[(size_t)B_ * NTAP * COUT * CIN];   // [b][t][o][i]
__device__ __half g_xt[(size_t)B_ * HH * WW * CIN];       // [b][y][x][i] NHWC

// ---------------- helpers ---------------------------------------------------
__device__ __forceinline__ uint32_t smem_u32(const void* p) {
    uint32_t a;
    asm("{ .reg .u64 t; cvta.to.shared.u64 t, %1; cvt.u32.u64 %0, t; }" : "=r"(a) : "l"(p));
    return a;
}
#define CPA16(s, g) \
    asm volatile("cp.async.cg.shared.global [%0], [%1], 16;" :: "r"(s), "l"(g) : "memory")
#define CPA_COMMIT() asm volatile("cp.async.commit_group;" ::: "memory")
#define CPA_WAIT(n)  asm volatile("cp.async.wait_group %0;" :: "n"(n) : "memory")

__device__ __forceinline__ void ldsm_x4(uint32_t* r, uint32_t addr) {
    asm volatile("ldmatrix.sync.aligned.m8n8.x4.shared.b16 {%0,%1,%2,%3}, [%4];"
                 : "=r"(r[0]), "=r"(r[1]), "=r"(r[2]), "=r"(r[3]) : "r"(addr));
}
__device__ __forceinline__ void ldsm_x2(uint32_t* r, uint32_t addr) {
    asm volatile("ldmatrix.sync.aligned.m8n8.x2.shared.b16 {%0,%1}, [%2];"
                 : "=r"(r[0]), "=r"(r[1]) : "r"(addr));
}
__device__ __forceinline__ void mma16816(float* c, const uint32_t* a, const uint32_t* b) {
    asm volatile(
        "mma.sync.aligned.m16n8k16.row.col.f32.f16.f16.f32 "
        "{%0,%1,%2,%3}, {%4,%5,%6,%7}, {%8,%9}, {%0,%1,%2,%3};"
        : "+f"(c[0]), "+f"(c[1]), "+f"(c[2]), "+f"(c[3])
        : "r"(a[0]), "r"(a[1]), "r"(a[2]), "r"(a[3]), "r"(b[0]), "r"(b[1]));
}

// ---------------------------------------------------------------------------
// Kernel 1: s[b][i] = style[b] . mod_w[i] + mod_b[i]
// ---------------------------------------------------------------------------
__global__ void modstyle_kernel(const float* __restrict__ style,
                                const float* __restrict__ mod_w,
                                const float* __restrict__ mod_b) {
    int b = blockIdx.y;
    int w = threadIdx.x >> 5, lane = threadIdx.x & 31;
    int i = blockIdx.x * 4 + w;

    const float4* mw = (const float4*)(mod_w + (size_t)i * SS);
    const float4* st = (const float4*)(style + (size_t)b * SS);
    float acc = 0.f;
#pragma unroll
    for (int j = 0; j < 4; j++) {
        float4 a = mw[lane + j * 32];
        float4 s4 = st[lane + j * 32];
        acc += a.x * s4.x + a.y * s4.y + a.z * s4.z + a.w * s4.w;
    }
#pragma unroll
    for (int off = 16; off > 0; off >>= 1)
        acc += __shfl_xor_sync(0xFFFFFFFFu, acc, off);
    if (lane == 0) g_s[b * CIN + i] = acc + mod_b[i];
}

// ---------------------------------------------------------------------------
// Kernel 2: demod -> fp16 weights, g_wA[b][t][o][i]
// ---------------------------------------------------------------------------
__global__ void demod_kernel(const float* __restrict__ weight) {
    int o = blockIdx.x, b = blockIdx.y, tid = threadIdx.x;
    __shared__ float s_sm[CIN];
    __shared__ float red[256];
    if (tid < CIN) s_sm[tid] = g_s[b * CIN + tid];
    __syncthreads();

    const float* w = weight + (size_t)o * CIN * NTAP;   // w[o][i][t]
    float p = 0.f;
    for (int idx = tid; idx < CIN * NTAP; idx += 256) {
        int i = idx / NTAP, t = idx - i * NTAP;
        float v = w[i * NTAP + t] * s_sm[i];
        p += v * v;
    }
    red[tid] = p;
    __syncthreads();
    for (int off = 128; off > 0; off >>= 1) {
        if (tid < off) red[tid] += red[tid + off];
        __syncthreads();
    }
    float dec = rsqrtf(red[0] + EPS);

    if (tid < CIN) {
        int i = tid;
        float sv = s_sm[i] * dec;
#pragma unroll
        for (int t = 0; t < NTAP; t++)
            g_wA[(((size_t)b * NTAP + t) * COUT + o) * CIN + i] =
                __float2half_rn(w[i * NTAP + t] * sv);
    }
}

// ---------------------------------------------------------------------------
// Kernel 3: NCHW fp32 -> NHWC fp16. grid (HH, B_), 256 threads
// ---------------------------------------------------------------------------
#define TSTR 130
__global__ void transpose_kernel(const float* __restrict__ x) {
    __shared__ __half T[WW * TSTR];
    int y = blockIdx.x, b = blockIdx.y, tid = threadIdx.x;
    const float* xb = x + ((size_t)b * CIN) * HH * WW + (size_t)y * WW;
    for (int idx = tid; idx < CIN * WW; idx += 256) {
        int i = idx >> 7, xx = idx & 127;
        T[xx * TSTR + i] = __float2half_rn(xb[(size_t)i * HH * WW + xx]);
    }
    __syncthreads();
    __half* dst = g_xt + (((size_t)b * HH + y) * WW) * CIN;
    for (int idx = tid; idx < WW * (CIN / 2); idx += 256) {
        int xx = idx >> 6, ip = idx & 63;
        uint32_t v = *(const uint32_t*)&T[xx * TSTR + 2 * ip];
        *(uint32_t*)&dst[(size_t)xx * CIN + 2 * ip] = v;
    }
}

// ---------------------------------------------------------------------------
// Kernel 4: mma.sync conv, quarter tile for 2 CTAs/SM.
// CTA = 128 threads (4 warps). Output tile o=64 x x=64 x 2 rows.
//   blockIdx.x = ypair*4 + quad;  o0=(quad&1)*64, x0=(quad>>1)*64, y=ypair*2.
//   Xpad[4][66][128ch] fp16 staged once (planes dy=-1..+2, halo p=0,65).
//   A[t] = g_wA[b][t][o0..o0+64) (64x128 f16), double-buffered cp.async.
// smem = 32 KB (A) + 67584 (X) = 100352 B -> 2 CTAs per SM.
// Warp tile 32(o) x 32(x) x 2 rows: wo=(wid&1)*32, wx=(wid>>1)*32.
// ---------------------------------------------------------------------------
#define SM_A     0
#define A_BYTES  16384
#define SM_X     (2 * A_BYTES)
#define XROWS    66
#define XPLANE   (XROWS * 256)
#define SM_TOTAL (SM_X + 4 * XPLANE)           // 32768 + 67584 = 100352

__device__ __forceinline__ uint32_t a_off(int buf, int r, int g) {
    return (uint32_t)(SM_A + buf * A_BYTES + r * 256 + ((g ^ (r & 7)) << 4));
}
__device__ __forceinline__ uint32_t x_off(int plane, int p, int g) {
    return (uint32_t)(SM_X + (plane * XROWS + p) * 256 + ((g ^ (p & 7)) << 4));
}

__global__ void __launch_bounds__(128, 2)
conv_mma_kernel(const __half* __restrict__ xt, float* __restrict__ out) {
    extern __shared__ __align__(1024) char smem[];
    uint32_t sb = smem_u32(smem);
    int quad = blockIdx.x & 3;
    int y  = (blockIdx.x >> 2) * 2;
    int o0 = (quad & 1) * 64;
    int x0 = (quad >> 1) * 64;
    int b = blockIdx.y;
    int tid = threadIdx.x, wid = tid >> 5, lane = tid & 31;

    const __half* wb = g_wA + ((size_t)b * NTAP) * COUT * CIN + (size_t)o0 * CIN;
    const __half* xb = xt + ((size_t)b * HH) * WW * CIN;

    // ---- stage Xpad (4 planes, once) + A0, group 0 ----
    for (int idx = tid; idx < 4 * XROWS * 16; idx += 128) {
        int plane = idx / (XROWS * 16);
        int rem = idx - plane * (XROWS * 16);
        int p = rem >> 4, g = rem & 15;
        int yy = y - 1 + plane, gx = x0 + p - 1;
        uint32_t sa = sb + x_off(plane, p, g);
        if (yy >= 0 && yy < HH && gx >= 0 && gx < WW) {
            CPA16(sa, xb + ((size_t)yy * WW + gx) * CIN + g * 8);
        } else {
            asm volatile("st.shared.v4.b32 [%0], {%1,%1,%1,%1};" :: "r"(sa), "r"(0u) : "memory");
        }
    }
#pragma unroll
    for (int it = 0; it < 8; it++) {
        int idx = tid + it * 128;
        int r = idx >> 4, g = idx & 15;
        CPA16(sb + a_off(0, r, g), wb + (size_t)r * CIN + g * 8);
    }
    CPA_COMMIT();
    // ---- A1, group 1 ----
#pragma unroll
    for (int it = 0; it < 8; it++) {
        int idx = tid + it * 128;
        int r = idx >> 4, g = idx & 15;
        CPA16(sb + a_off(1, r, g), wb + (size_t)(COUT * CIN) + (size_t)r * CIN + g * 8);
    }
    CPA_COMMIT();

    int wo = (wid & 1) * 32;       // local o base (0/32)
    int wx = (wid >> 1) * 32;      // local x base (0/32)
    float acc[2][2][4][4];
#pragma unroll
    for (int yr = 0; yr < 2; yr++)
#pragma unroll
        for (int mt = 0; mt < 2; mt++)
#pragma unroll
            for (int nt = 0; nt < 4; nt++)
#pragma unroll
                for (int q = 0; q < 4; q++) acc[yr][mt][nt][q] = 0.f;

    for (int t = 0; t < NTAP; t++) {
        if (t < 8) { CPA_WAIT(1); } else { CPA_WAIT(0); }
        __syncthreads();

        int buf = t & 1;
        int dy = t / 3, dx = t - 3 * dy;

        int ar_l = lane & 15, ac_g2 = (lane >> 4);
        int br_l = (lane & 7), bg_sel = (lane >> 3) & 1;

#pragma unroll
        for (int ks = 0; ks < 8; ks++) {
            uint32_t afr[2][4];
            uint32_t bfr[2][4][2];
#pragma unroll
            for (int mt = 0; mt < 2; mt++) {
                int r = wo + mt * 16 + ar_l;
                ldsm_x4(afr[mt], sb + a_off(buf, r, ks * 2 + ac_g2));
            }
#pragma unroll
            for (int yr = 0; yr < 2; yr++) {
#pragma unroll
                for (int nt = 0; nt < 4; nt++) {
                    int p = wx + nt * 8 + br_l + dx;
                    ldsm_x2(bfr[yr][nt], sb + x_off(dy + yr, p, ks * 2 + bg_sel));
                }
            }
#pragma unroll
            for (int yr = 0; yr < 2; yr++)
#pragma unroll
                for (int mt = 0; mt < 2; mt++)
#pragma unroll
                    for (int nt = 0; nt < 4; nt++)
                        mma16816(acc[yr][mt][nt], afr[mt], bfr[yr][nt]);
        }
        __syncthreads();
        // prefetch A for tap t+2 into the buffer just freed
        if (t + 2 < NTAP) {
            const __half* asrc = wb + (size_t)(t + 2) * COUT * CIN;
#pragma unroll
            for (int it = 0; it < 8; it++) {
                int idx = tid + it * 128;
                int r = idx >> 4, g = idx & 15;
                CPA16(sb + a_off(buf, r, g), asrc + (size_t)r * CIN + g * 8);
            }
        }
        CPA_COMMIT();   // keep group count in lockstep even when empty
    }

    // ---- epilogue: c frags -> out[b][o0+o][y+yr][x0+x] ----
    int ml = lane >> 2, nl = (lane & 3) * 2;
#pragma unroll
    for (int yr = 0; yr < 2; yr++) {
        float* ob = out + ((size_t)b * COUT) * HH * WW + (size_t)(y + yr) * WW;
#pragma unroll
        for (int mt = 0; mt < 2; mt++) {
#pragma unroll
            for (int half = 0; half < 2; half++) {
                int o = o0 + wo + mt * 16 + ml + half * 8;
                float* orow = ob + (size_t)o * HH * WW;
#pragma unroll
                for (int nt = 0; nt < 4; nt++) {
                    int xx = x0 + wx + nt * 8 + nl;
                    float2 v;
                    v.x = acc[yr][mt][nt][half * 2 + 0];
                    v.y = acc[yr][mt][nt][half * 2 + 1];
                    *(float2*)(orow + xx) = v;
                }
            }
        }
    }
}

// ---------------------------------------------------------------------------
extern "C" void kernel_launch(void* const* d_in, const int* in_sizes, int n_in,
                              void* d_out, int out_size) {
    const float* x      = (const float*)d_in[0];
    const float* style  = (const float*)d_in[1];
    const float* weight = (const float*)d_in[2];
    const float* mod_w  = (const float*)d_in[3];
    const float* mod_b  = (const float*)d_in[4];
    float* out = (float*)d_out;

    modstyle_kernel<<<dim3(CIN / 4, B_), 128>>>(style, mod_w, mod_b);
    demod_kernel<<<dim3(COUT, B_), 256>>>(weight);
    transpose_kernel<<<dim3(HH, B_), 256>>>(x);

    __half* xt_ptr = nullptr;
    cudaGetSymbolAddress((void**)&xt_ptr, g_xt);
    cudaFuncSetAttribute(conv_mma_kernel, cudaFuncAttributeMaxDynamicSharedMemorySize, SM_TOTAL);
    conv_mma_kernel<<<dim3((HH / 2) * 4, B_), 128, SM_TOTAL>>>(xt_ptr, out);
}

// round 7
// speedup vs baseline: 1.0027x; 1.0027x over previous
#include <cuda_runtime.h>
#include <cuda_fp16.h>
#include <cstdint>
#include <cstddef>

#define EPS 1e-8f
#define B_   16
#define CIN  128
#define COUT 128
#define HH   128
#define WW   128
#define SS   512
#define NTAP 9

// ---------------- scratch (__device__ globals; no allocs allowed) ----------
__device__ float  g_s[B_ * CIN];
__device__ __half g_wA[(size_t)B_ * NTAP * COUT * CIN];   // [b][t][o][i]
__device__ __half g_xt[(size_t)B_ * HH * WW * CIN];       // [b][y][x][i] NHWC

// ---------------- helpers ---------------------------------------------------
__device__ __forceinline__ uint32_t smem_u32(const void* p) {
    uint32_t a;
    asm("{ .reg .u64 t; cvta.to.shared.u64 t, %1; cvt.u32.u64 %0, t; }" : "=r"(a) : "l"(p));
    return a;
}
#define CPA16(s, g) \
    asm volatile("cp.async.cg.shared.global [%0], [%1], 16;" :: "r"(s), "l"(g) : "memory")
#define CPA_COMMIT() asm volatile("cp.async.commit_group;" ::: "memory")
#define CPA_WAIT(n)  asm volatile("cp.async.wait_group %0;" :: "n"(n) : "memory")

__device__ __forceinline__ void ldsm_x4(uint32_t* r, uint32_t addr) {
    asm volatile("ldmatrix.sync.aligned.m8n8.x4.shared.b16 {%0,%1,%2,%3}, [%4];"
                 : "=r"(r[0]), "=r"(r[1]), "=r"(r[2]), "=r"(r[3]) : "r"(addr));
}
__device__ __forceinline__ void mma16816(float* c, const uint32_t* a, const uint32_t* b) {
    asm volatile(
        "mma.sync.aligned.m16n8k16.row.col.f32.f16.f16.f32 "
        "{%0,%1,%2,%3}, {%4,%5,%6,%7}, {%8,%9}, {%0,%1,%2,%3};"
        : "+f"(c[0]), "+f"(c[1]), "+f"(c[2]), "+f"(c[3])
        : "r"(a[0]), "r"(a[1]), "r"(a[2]), "r"(a[3]), "r"(b[0]), "r"(b[1]));
}

// ---------------------------------------------------------------------------
// Kernel 1: s[b][i] = style[b] . mod_w[i] + mod_b[i]
// ---------------------------------------------------------------------------
__global__ void modstyle_kernel(const float* __restrict__ style,
                                const float* __restrict__ mod_w,
                                const float* __restrict__ mod_b) {
    int b = blockIdx.y;
    int w = threadIdx.x >> 5, lane = threadIdx.x & 31;
    int i = blockIdx.x * 4 + w;

    const float4* mw = (const float4*)(mod_w + (size_t)i * SS);
    const float4* st = (const float4*)(style + (size_t)b * SS);
    float acc = 0.f;
#pragma unroll
    for (int j = 0; j < 4; j++) {
        float4 a = mw[lane + j * 32];
        float4 s4 = st[lane + j * 32];
        acc += a.x * s4.x + a.y * s4.y + a.z * s4.z + a.w * s4.w;
    }
#pragma unroll
    for (int off = 16; off > 0; off >>= 1)
        acc += __shfl_xor_sync(0xFFFFFFFFu, acc, off);
    if (lane == 0) g_s[b * CIN + i] = acc + mod_b[i];
}

// ---------------------------------------------------------------------------
// Kernel 2: demod -> fp16 weights, g_wA[b][t][o][i]
// ---------------------------------------------------------------------------
__global__ void demod_kernel(const float* __restrict__ weight) {
    int o = blockIdx.x, b = blockIdx.y, tid = threadIdx.x;
    __shared__ float s_sm[CIN];
    __shared__ float red[256];
    if (tid < CIN) s_sm[tid] = g_s[b * CIN + tid];
    __syncthreads();

    const float* w = weight + (size_t)o * CIN * NTAP;   // w[o][i][t]
    float p = 0.f;
    for (int idx = tid; idx < CIN * NTAP; idx += 256) {
        int i = idx / NTAP, t = idx - i * NTAP;
        float v = w[i * NTAP + t] * s_sm[i];
        p += v * v;
    }
    red[tid] = p;
    __syncthreads();
    for (int off = 128; off > 0; off >>= 1) {
        if (tid < off) red[tid] += red[tid + off];
        __syncthreads();
    }
    float dec = rsqrtf(red[0] + EPS);

    if (tid < CIN) {
        int i = tid;
        float sv = s_sm[i] * dec;
#pragma unroll
        for (int t = 0; t < NTAP; t++)
            g_wA[(((size_t)b * NTAP + t) * COUT + o) * CIN + i] =
                __float2half_rn(w[i * NTAP + t] * sv);
    }
}

// ---------------------------------------------------------------------------
// Kernel 3: NCHW fp32 -> NHWC fp16. grid (HH, B_), 256 threads
// ---------------------------------------------------------------------------
#define TSTR 130
__global__ void transpose_kernel(const float* __restrict__ x) {
    __shared__ __half T[WW * TSTR];
    int y = blockIdx.x, b = blockIdx.y, tid = threadIdx.x;
    const float* xb = x + ((size_t)b * CIN) * HH * WW + (size_t)y * WW;
    for (int idx = tid; idx < CIN * WW; idx += 256) {
        int i = idx >> 7, xx = idx & 127;
        T[xx * TSTR + i] = __float2half_rn(xb[(size_t)i * HH * WW + xx]);
    }
    __syncthreads();
    __half* dst = g_xt + (((size_t)b * HH + y) * WW) * CIN;
    for (int idx = tid; idx < WW * (CIN / 2); idx += 256) {
        int xx = idx >> 6, ip = idx & 63;
        uint32_t v = *(const uint32_t*)&T[xx * TSTR + 2 * ip];
        *(uint32_t*)&dst[(size_t)xx * CIN + 2 * ip] = v;
    }
}

// ---------------------------------------------------------------------------
// Kernel 4: mma.sync conv, FOUR output rows per CTA, x-halved.
// CTA = 256 threads (8 warps). Output tile o=128 x x=64 x 4 rows.
//   blockIdx.x = ygrp*2 + xh; y = ygrp*4, x0 = xh*64.
//   Xpad[6][66][128ch] fp16 staged once (planes dy=-1..+4, halo p=0,65).
//   A[t] = g_wA[b][t] (128x128 f16), double-buffered cp.async, reused by 4 rows.
// smem = 64 KB (A) + 6*66*256 (X) = 166912 B -> 1 CTA/SM.
// Warp tile 64(o) x 16(x) x 4 rows: wo=(wid&1)*64, wx=(wid>>1)*16.
// Per k16: 4 ldsm_x4 (A) + 4 ldsm_x4 (B: nt-pair x granule-pair) -> 32 MMA.
// ---------------------------------------------------------------------------
#define SM_A     0
#define A_BYTES  32768
#define SM_X     (2 * A_BYTES)
#define XROWS    66
#define XPLANE   (XROWS * 256)
#define SM_TOTAL (SM_X + 6 * XPLANE)           // 65536 + 101376 = 166912

__device__ __forceinline__ uint32_t a_off(int buf, int r, int g) {
    return (uint32_t)(SM_A + buf * A_BYTES + r * 256 + ((g ^ (r & 7)) << 4));
}
__device__ __forceinline__ uint32_t x_off(int plane, int p, int g) {
    return (uint32_t)(SM_X + (plane * XROWS + p) * 256 + ((g ^ (p & 7)) << 4));
}

__global__ void __launch_bounds__(256, 1)
conv_mma_kernel(const __half* __restrict__ xt, float* __restrict__ out) {
    extern __shared__ __align__(1024) char smem[];
    uint32_t sb = smem_u32(smem);
    int xh = blockIdx.x & 1;
    int y  = (blockIdx.x >> 1) * 4;
    int x0 = xh * 64;
    int b = blockIdx.y;
    int tid = threadIdx.x, wid = tid >> 5, lane = tid & 31;

    const __half* wb = g_wA + ((size_t)b * NTAP) * COUT * CIN;
    const __half* xb = xt + ((size_t)b * HH) * WW * CIN;

    // ---- stage Xpad (6 planes, once) + A0, group 0 ----
    for (int idx = tid; idx < 6 * XROWS * 16; idx += 256) {
        int plane = idx / (XROWS * 16);
        int rem = idx - plane * (XROWS * 16);
        int p = rem >> 4, g = rem & 15;
        int yy = y - 1 + plane, gx = x0 + p - 1;
        uint32_t sa = sb + x_off(plane, p, g);
        if (yy >= 0 && yy < HH && gx >= 0 && gx < WW) {
            CPA16(sa, xb + ((size_t)yy * WW + gx) * CIN + g * 8);
        } else {
            asm volatile("st.shared.v4.b32 [%0], {%1,%1,%1,%1};" :: "r"(sa), "r"(0u) : "memory");
        }
    }
#pragma unroll
    for (int it = 0; it < 8; it++) {
        int idx = tid + it * 256;
        int r = idx >> 4, g = idx & 15;
        CPA16(sb + a_off(0, r, g), wb + (size_t)r * CIN + g * 8);
    }
    CPA_COMMIT();
    // ---- A1, group 1 ----
#pragma unroll
    for (int it = 0; it < 8; it++) {
        int idx = tid + it * 256;
        int r = idx >> 4, g = idx & 15;
        CPA16(sb + a_off(1, r, g), wb + (size_t)(COUT * CIN) + (size_t)r * CIN + g * 8);
    }
    CPA_COMMIT();

    int wo = (wid & 1) * 64;       // o base
    int wx = (wid >> 1) * 16;      // x base (0/16/32/48)
    float acc[4][4][2][4];
#pragma unroll
    for (int yr = 0; yr < 4; yr++)
#pragma unroll
        for (int mt = 0; mt < 4; mt++)
#pragma unroll
            for (int nt = 0; nt < 2; nt++)
#pragma unroll
                for (int q = 0; q < 4; q++) acc[yr][mt][nt][q] = 0.f;

    for (int t = 0; t < NTAP; t++) {
        if (t < 8) { CPA_WAIT(1); } else { CPA_WAIT(0); }
        __syncthreads();

        int buf = t & 1;
        int dy = t / 3, dx = t - 3 * dy;

        // A x4: row = wo + mt*16 + (lane&15), granule selects k-half via lane>>4
        int ar_l = lane & 15, ac_g2 = (lane >> 4);
        // B x4: lane quarters -> (nt_sel = (lane>>4)&1, g_sel = (lane>>3)&1)
        int bnt = (lane >> 4) & 1, bg = (lane >> 3) & 1, br_l = lane & 7;

#pragma unroll
        for (int ks = 0; ks < 8; ks++) {
            uint32_t afr[4][4];
            uint32_t bfr[4][4];
#pragma unroll
            for (int mt = 0; mt < 4; mt++) {
                int r = wo + mt * 16 + ar_l;
                ldsm_x4(afr[mt], sb + a_off(buf, r, ks * 2 + ac_g2));
            }
#pragma unroll
            for (int yr = 0; yr < 4; yr++) {
                int p = wx + bnt * 8 + br_l + dx;
                ldsm_x4(bfr[yr], sb + x_off(dy + yr, p, ks * 2 + bg));
            }
#pragma unroll
            for (int yr = 0; yr < 4; yr++)
#pragma unroll
                for (int mt = 0; mt < 4; mt++)
#pragma unroll
                    for (int nt = 0; nt < 2; nt++)
                        mma16816(acc[yr][mt][nt], afr[mt], &bfr[yr][nt * 2]);
        }
        __syncthreads();
        // prefetch A for tap t+2 into the buffer just freed
        if (t + 2 < NTAP) {
            const __half* asrc = wb + (size_t)(t + 2) * COUT * CIN;
#pragma unroll
            for (int it = 0; it < 8; it++) {
                int idx = tid + it * 256;
                int r = idx >> 4, g = idx & 15;
                CPA16(sb + a_off(buf, r, g), asrc + (size_t)r * CIN + g * 8);
            }
        }
        CPA_COMMIT();   // keep group count in lockstep even when empty
    }

    // ---- epilogue: c frags -> out[b][o][y+yr][x0+x] ----
    int ml = lane >> 2, nl = (lane & 3) * 2;
#pragma unroll
    for (int yr = 0; yr < 4; yr++) {
        float* ob = out + ((size_t)b * COUT) * HH * WW + (size_t)(y + yr) * WW;
#pragma unroll
        for (int mt = 0; mt < 4; mt++) {
#pragma unroll
            for (int half = 0; half < 2; half++) {
                int o = wo + mt * 16 + ml + half * 8;
                float* orow = ob + (size_t)o * HH * WW;
#pragma unroll
                for (int nt = 0; nt < 2; nt++) {
                    int xx = x0 + wx + nt * 8 + nl;
                    float2 v;
                    v.x = acc[yr][mt][nt][half * 2 + 0];
                    v.y = acc[yr][mt][nt][half * 2 + 1];
                    *(float2*)(orow + xx) = v;
                }
            }
        }
    }
}

// ---------------------------------------------------------------------------
extern "C" void kernel_launch(void* const* d_in, const int* in_sizes, int n_in,
                              void* d_out, int out_size) {
    const float* x      = (const float*)d_in[0];
    const float* style  = (const float*)d_in[1];
    const float* weight = (const float*)d_in[2];
    const float* mod_w  = (const float*)d_in[3];
    const float* mod_b  = (const float*)d_in[4];
    float* out = (float*)d_out;

    modstyle_kernel<<<dim3(CIN / 4, B_), 128>>>(style, mod_w, mod_b);
    demod_kernel<<<dim3(COUT, B_), 256>>>(weight);
    transpose_kernel<<<dim3(HH, B_), 256>>>(x);

    __half* xt_ptr = nullptr;
    cudaGetSymbolAddress((void**)&xt_ptr, g_xt);
    cudaFuncSetAttribute(conv_mma_kernel, cudaFuncAttributeMaxDynamicSharedMemorySize, SM_TOTAL);
    conv_mma_kernel<<<dim3((HH / 4) * 2, B_), 256, SM_TOTAL>>>(xt_ptr, out);
}

// round 8
// speedup vs baseline: 1.0737x; 1.0708x over previous
#include <cuda_runtime.h>
#include <cuda_fp16.h>
#include <cstdint>
#include <cstddef>

#define EPS 1e-8f
#define B_   16
#define CIN  128
#define COUT 128
#define HH   128
#define WW   128
#define SS   512
#define NTAP 9

// ---------------- scratch (__device__ globals; no allocs allowed) ----------
__device__ float  g_s[B_ * CIN];
__device__ __half g_wA[(size_t)B_ * NTAP * COUT * CIN];   // [b][t][o][i]
__device__ __half g_xt[(size_t)B_ * HH * WW * CIN];       // [b][y][x][i] NHWC

// ---------------- helpers ---------------------------------------------------
__device__ __forceinline__ uint32_t smem_u32(const void* p) {
    uint32_t a;
    asm("{ .reg .u64 t; cvta.to.shared.u64 t, %1; cvt.u32.u64 %0, t; }" : "=r"(a) : "l"(p));
    return a;
}
#define CPA16(s, g) \
    asm volatile("cp.async.cg.shared.global [%0], [%1], 16;" :: "r"(s), "l"(g) : "memory")
#define CPA_COMMIT() asm volatile("cp.async.commit_group;" ::: "memory")
#define CPA_WAIT(n)  asm volatile("cp.async.wait_group %0;" :: "n"(n) : "memory")

__device__ __forceinline__ void ldsm_x4(uint32_t* r, uint32_t addr) {
    asm volatile("ldmatrix.sync.aligned.m8n8.x4.shared.b16 {%0,%1,%2,%3}, [%4];"
                 : "=r"(r[0]), "=r"(r[1]), "=r"(r[2]), "=r"(r[3]) : "r"(addr));
}
__device__ __forceinline__ void mma16816(float* c, const uint32_t* a, const uint32_t* b) {
    asm volatile(
        "mma.sync.aligned.m16n8k16.row.col.f32.f16.f16.f32 "
        "{%0,%1,%2,%3}, {%4,%5,%6,%7}, {%8,%9}, {%0,%1,%2,%3};"
        : "+f"(c[0]), "+f"(c[1]), "+f"(c[2]), "+f"(c[3])
        : "r"(a[0]), "r"(a[1]), "r"(a[2]), "r"(a[3]), "r"(b[0]), "r"(b[1]));
}

// ---------------------------------------------------------------------------
// Kernel 1: s[b][i] = style[b] . mod_w[i] + mod_b[i]  (tiny)
// ---------------------------------------------------------------------------
__global__ void modstyle_kernel(const float* __restrict__ style,
                                const float* __restrict__ mod_w,
                                const float* __restrict__ mod_b) {
    int b = blockIdx.y;
    int w = threadIdx.x >> 5, lane = threadIdx.x & 31;
    int i = blockIdx.x * 4 + w;

    const float4* mw = (const float4*)(mod_w + (size_t)i * SS);
    const float4* st = (const float4*)(style + (size_t)b * SS);
    float acc = 0.f;
#pragma unroll
    for (int j = 0; j < 4; j++) {
        float4 a = mw[lane + j * 32];
        float4 s4 = st[lane + j * 32];
        acc += a.x * s4.x + a.y * s4.y + a.z * s4.z + a.w * s4.w;
    }
#pragma unroll
    for (int off = 16; off > 0; off >>= 1)
        acc += __shfl_xor_sync(0xFFFFFFFFu, acc, off);
    if (lane == 0) g_s[b * CIN + i] = acc + mod_b[i];
}

// ---------------------------------------------------------------------------
// Kernel 2 (FUSED): blocks [0,2048) transpose NCHW->NHWC fp16;
//                   blocks [2048,4096) demod -> g_wA. Runs concurrently.
// ---------------------------------------------------------------------------
#define TSTR 130
__global__ void __launch_bounds__(256)
prep_kernel(const float* __restrict__ x, const float* __restrict__ weight) {
    __shared__ __half T[WW * TSTR];     // used by transpose role only (33 KB)
    __shared__ float s_sm[CIN];
    __shared__ float red[256];
    int tid = threadIdx.x;

    if (blockIdx.x < 2048) {
        // ---- transpose role: blk -> (b, y) ----
        int blk = blockIdx.x;
        int b = blk >> 7, y = blk & 127;
        const float* xb = x + ((size_t)b * CIN) * HH * WW + (size_t)y * WW;
        for (int idx = tid; idx < CIN * WW; idx += 256) {
            int i = idx >> 7, xx = idx & 127;
            T[xx * TSTR + i] = __float2half_rn(xb[(size_t)i * HH * WW + xx]);
        }
        __syncthreads();
        __half* dst = g_xt + (((size_t)b * HH + y) * WW) * CIN;
        for (int idx = tid; idx < WW * (CIN / 2); idx += 256) {
            int xx = idx >> 6, ip = idx & 63;
            uint32_t v = *(const uint32_t*)&T[xx * TSTR + 2 * ip];
            *(uint32_t*)&dst[(size_t)xx * CIN + 2 * ip] = v;
        }
    } else {
        // ---- demod role: blk -> (b, o) ----
        int blk = blockIdx.x - 2048;
        int b = blk >> 7, o = blk & 127;
        if (tid < CIN) s_sm[tid] = g_s[b * CIN + tid];
        __syncthreads();

        const float* w = weight + (size_t)o * CIN * NTAP;   // w[o][i][t]
        float p = 0.f;
        for (int idx = tid; idx < CIN * NTAP; idx += 256) {
            int i = idx / NTAP, t = idx - i * NTAP;
            float v = w[i * NTAP + t] * s_sm[i];
            p += v * v;
        }
        red[tid] = p;
        __syncthreads();
        for (int off = 128; off > 0; off >>= 1) {
            if (tid < off) red[tid] += red[tid + off];
            __syncthreads();
        }
        float dec = rsqrtf(red[0] + EPS);

        if (tid < CIN) {
            int i = tid;
            float sv = s_sm[i] * dec;
#pragma unroll
            for (int t = 0; t < NTAP; t++)
                g_wA[(((size_t)b * NTAP + t) * COUT + o) * CIN + i] =
                    __float2half_rn(w[i * NTAP + t] * sv);
        }
    }
}

// ---------------------------------------------------------------------------
// Kernel 3: mma.sync conv, FOUR output rows per CTA, x-halved, A TRIPLE-buffered.
// CTA = 256 threads (8 warps). Output tile o=128 x x=64 x 4 rows.
//   blockIdx.x = ygrp*2 + xh; y = ygrp*4, x0 = xh*64.
//   Xpad[6][66][128ch] fp16 staged once (planes dy=-1..+4, halo p=0,65).
//   A[t] -> buf t%3; prefetch A[t+2] -> buf (t+2)%3 post-mainloop, NO 2nd sync.
// smem = 3*32768 (A) + 6*66*256 (X) = 199680 B -> 1 CTA/SM.
// Warp tile 64(o) x 16(x) x 4 rows. Per k16: 4 ldsm_x4 A + 4 ldsm_x4 B -> 32 MMA.
// Commit groups: G0 = {X planes 0..3, A0}, G1 = {X planes 4..5, A1},
// then one group per tap (A[t+2] or empty). At tap t: committed = 2+t,
// CPA_WAIT(1) completes G0..G(t) -> A[t] and all needed planes ready.
// ---------------------------------------------------------------------------
#define SM_A     0
#define A_BYTES  32768
#define SM_X     (3 * A_BYTES)
#define XROWS    66
#define XPLANE   (XROWS * 256)
#define SM_TOTAL (SM_X + 6 * XPLANE)           // 98304 + 101376 = 199680

__device__ __forceinline__ uint32_t a_off(int buf, int r, int g) {
    return (uint32_t)(SM_A + buf * A_BYTES + r * 256 + ((g ^ (r & 7)) << 4));
}
__device__ __forceinline__ uint32_t x_off(int plane, int p, int g) {
    return (uint32_t)(SM_X + (plane * XROWS + p) * 256 + ((g ^ (p & 7)) << 4));
}

__global__ void __launch_bounds__(256, 1)
conv_mma_kernel(const __half* __restrict__ xt, float* __restrict__ out) {
    extern __shared__ __align__(1024) char smem[];
    uint32_t sb = smem_u32(smem);
    int xh = blockIdx.x & 1;
    int y  = (blockIdx.x >> 1) * 4;
    int x0 = xh * 64;
    int b = blockIdx.y;
    int tid = threadIdx.x, wid = tid >> 5, lane = tid & 31;

    const __half* wb = g_wA + ((size_t)b * NTAP) * COUT * CIN;
    const __half* xb = xt + ((size_t)b * HH) * WW * CIN;

    // ---- G0: X planes 0..3 + A0 ----
    for (int idx = tid; idx < 4 * XROWS * 16; idx += 256) {
        int plane = idx / (XROWS * 16);
        int rem = idx - plane * (XROWS * 16);
        int p = rem >> 4, g = rem & 15;
        int yy = y - 1 + plane, gx = x0 + p - 1;
        uint32_t sa = sb + x_off(plane, p, g);
        if (yy >= 0 && yy < HH && gx >= 0 && gx < WW) {
            CPA16(sa, xb + ((size_t)yy * WW + gx) * CIN + g * 8);
        } else {
            asm volatile("st.shared.v4.b32 [%0], {%1,%1,%1,%1};" :: "r"(sa), "r"(0u) : "memory");
        }
    }
#pragma unroll
    for (int it = 0; it < 8; it++) {
        int idx = tid + it * 256;
        int r = idx >> 4, g = idx & 15;
        CPA16(sb + a_off(0, r, g), wb + (size_t)r * CIN + g * 8);
    }
    CPA_COMMIT();
    // ---- G1: X planes 4..5 + A1 ----
    for (int idx = tid; idx < 2 * XROWS * 16; idx += 256) {
        int plane = 4 + idx / (XROWS * 16);
        int rem = idx % (XROWS * 16);
        int p = rem >> 4, g = rem & 15;
        int yy = y - 1 + plane, gx = x0 + p - 1;
        uint32_t sa = sb + x_off(plane, p, g);
        if (yy >= 0 && yy < HH && gx >= 0 && gx < WW) {
            CPA16(sa, xb + ((size_t)yy * WW + gx) * CIN + g * 8);
        } else {
            asm volatile("st.shared.v4.b32 [%0], {%1,%1,%1,%1};" :: "r"(sa), "r"(0u) : "memory");
        }
    }
#pragma unroll
    for (int it = 0; it < 8; it++) {
        int idx = tid + it * 256;
        int r = idx >> 4, g = idx & 15;
        CPA16(sb + a_off(1, r, g), wb + (size_t)(COUT * CIN) + (size_t)r * CIN + g * 8);
    }
    CPA_COMMIT();

    int wo = (wid & 1) * 64;       // o base
    int wx = (wid >> 1) * 16;      // x base (0/16/32/48)
    float acc[4][4][2][4];
#pragma unroll
    for (int yr = 0; yr < 4; yr++)
#pragma unroll
        for (int mt = 0; mt < 4; mt++)
#pragma unroll
            for (int nt = 0; nt < 2; nt++)
#pragma unroll
                for (int q = 0; q < 4; q++) acc[yr][mt][nt][q] = 0.f;

    for (int t = 0; t < NTAP; t++) {
        CPA_WAIT(1);
        __syncthreads();            // the ONLY barrier per tap

        int buf = t % 3;
        int dy = t / 3, dx = t - 3 * dy;

        int ar_l = lane & 15, ac_g2 = (lane >> 4);
        int bnt = (lane >> 4) & 1, bg = (lane >> 3) & 1, br_l = lane & 7;

#pragma unroll
        for (int ks = 0; ks < 8; ks++) {
            uint32_t afr[4][4];
            uint32_t bfr[4][4];
#pragma unroll
            for (int mt = 0; mt < 4; mt++) {
                int r = wo + mt * 16 + ar_l;
                ldsm_x4(afr[mt], sb + a_off(buf, r, ks * 2 + ac_g2));
            }
#pragma unroll
            for (int yr = 0; yr < 4; yr++) {
                int p = wx + bnt * 8 + br_l + dx;
                ldsm_x4(bfr[yr], sb + x_off(dy + yr, p, ks * 2 + bg));
            }
#pragma unroll
            for (int yr = 0; yr < 4; yr++)
#pragma unroll
                for (int mt = 0; mt < 4; mt++)
#pragma unroll
                    for (int nt = 0; nt < 2; nt++)
                        mma16816(acc[yr][mt][nt], afr[mt], &bfr[yr][nt * 2]);
        }
        // prefetch A for tap t+2 into buf (t+2)%3 — untouched by any current reader
        if (t + 2 < NTAP) {
            int pbuf = (t + 2) % 3;
            const __half* asrc = wb + (size_t)(t + 2) * COUT * CIN;
#pragma unroll
            for (int it = 0; it < 8; it++) {
                int idx = tid + it * 256;
                int r = idx >> 4, g = idx & 15;
                CPA16(sb + a_off(pbuf, r, g), asrc + (size_t)r * CIN + g * 8);
            }
        }
        CPA_COMMIT();   // one group per tap, possibly empty, keeps count in lockstep
    }

    // ---- epilogue: c frags -> out[b][o][y+yr][x0+x] ----
    int ml = lane >> 2, nl = (lane & 3) * 2;
#pragma unroll
    for (int yr = 0; yr < 4; yr++) {
        float* ob = out + ((size_t)b * COUT) * HH * WW + (size_t)(y + yr) * WW;
#pragma unroll
        for (int mt = 0; mt < 4; mt++) {
#pragma unroll
            for (int half = 0; half < 2; half++) {
                int o = wo + mt * 16 + ml + half * 8;
                float* orow = ob + (size_t)o * HH * WW;
#pragma unroll
                for (int nt = 0; nt < 2; nt++) {
                    int xx = x0 + wx + nt * 8 + nl;
                    float2 v;
                    v.x = acc[yr][mt][nt][half * 2 + 0];
                    v.y = acc[yr][mt][nt][half * 2 + 1];
                    *(float2*)(orow + xx) = v;
                }
            }
        }
    }
}

// ---------------------------------------------------------------------------
extern "C" void kernel_launch(void* const* d_in, const int* in_sizes, int n_in,
                              void* d_out, int out_size) {
    const float* x      = (const float*)d_in[0];
    const float* style  = (const float*)d_in[1];
    const float* weight = (const float*)d_in[2];
    const float* mod_w  = (const float*)d_in[3];
    const float* mod_b  = (const float*)d_in[4];
    float* out = (float*)d_out;

    modstyle_kernel<<<dim3(CIN / 4, B_), 128>>>(style, mod_w, mod_b);
    prep_kernel<<<4096, 256>>>(x, weight);

    __half* xt_ptr = nullptr;
    cudaGetSymbolAddress((void**)&xt_ptr, g_xt);
    cudaFuncSetAttribute(conv_mma_kernel, cudaFuncAttributeMaxDynamicSharedMemorySize, SM_TOTAL);
    conv_mma_kernel<<<dim3((HH / 4) * 2, B_), 256, SM_TOTAL>>>(xt_ptr, out);
}